// round 1
// baseline (speedup 1.0000x reference)
#include <cuda_runtime.h>
#include <math.h>

#define GD 60
#define GG 3600
#define TB 32
#define NTHREADS 256

struct Params {
    const float* mv;      // 0 (1,2,60,60)
    const float* boxes;   // 1 (4096,4)
    const float* W_stats; // 2 (64,6)
    const float* b_stats; // 3
    const float* g_stats; // 4
    const float* be_stats;// 5
    const float* W_b1;    // 6 (32,4)
    const float* b_b1;    // 7
    const float* g_b1;    // 8
    const float* be_b1;   // 9
    const float* W_b2;    // 10 (32,32)
    const float* b_b2;    // 11
    const float* g_b2;    // 12
    const float* be_b2;   // 13
    const float* W_ih;    // 14 (512,96)
    const float* W_hh;    // 15 (unused: h0=0)
    const float* b_ih;    // 16
    const float* b_hh;    // 17
    const float* W_p1;    // 18 (64,128)
    const float* b_p1;    // 19
    const float* W_p2;    // 20 (2,64)
    const float* b_p2;    // 21
    const float* W_s1;    // 22
    const float* b_s1;    // 23
    const float* W_s2;    // 24
    const float* b_s2;    // 25
    const float* W_c1;    // 26
    const float* b_c1;    // 27
    const float* W_c2;    // 28 (1,64)
    const float* b_c2;    // 29
    float* out;
};

__device__ __forceinline__ float sigmoidf_(float x) {
    return 1.0f / (1.0f + expf(-x));
}

// Shared memory layout (bytes):
//   x_s   @ 0       : 32*96*4            = 12288
//   wbuf  @ 12288   : max(mv 28800, Wt_g 384*17*4=26112, Wt_h 192*33*4=25344) = 28800
//   big   @ 41088   : 16384 floats       = 65536
// total = 106624
#define SMEM_BYTES 106624

__global__ void __launch_bounds__(NTHREADS, 1)
tracker_fused_kernel(Params p) {
    extern __shared__ char smem[];
    float* x_s  = (float*)smem;                 // [32][96]
    float* wbuf = (float*)(smem + 12288);
    float* big  = (float*)(smem + 41088);       // 16384 floats

    // phase-A views into big
    float* stats_s = big;            // 192
    float* bn_s    = big + 192;      // 128
    float* zA      = big + 320;      // 2048  [32][64]
    float* zB      = big + 2368;     // 1024  [32][32]
    float* h1_s    = big + 3392;     // 1024  [32][32]
    // phase-B views
    float* gates_s = big;            // [32][384] = 12288
    float* h_s     = big + 12288;    // [32][128] = 4096  (ends at 16384)
    float* hid_s   = big;            // [32][192] = 6144  (after gates dead)
    float* fin_s   = big + 6144;     // 160

    const int tid  = threadIdx.x;
    const int lane = tid & 31;
    const int w    = tid >> 5;       // warp id 0..7
    const int box0 = blockIdx.x * TB;

    // ---------------- Phase A0: stage motion field, boxes_norm ----------------
    for (int i = tid; i < 2 * GG; i += NTHREADS) wbuf[i] = p.mv[i];
    if (tid < TB * 4) {
        int b = tid >> 2, c = tid & 3;
        float v = p.boxes[(box0 + b) * 4 + c] / 960.0f;
        bn_s[b * 4 + c] = fminf(fmaxf(v, 0.0f), 1.0f);
    }
    __syncthreads();

    // ---------------- Phase A1: box-motion stats (warp per box) ----------------
    for (int bb = 0; bb < 4; bb++) {
        int b = w * 4 + bb;
        int x1 = min(max((int)floorf(bn_s[b * 4 + 0] * 60.0f), 0), GD - 1);
        int y1 = min(max((int)floorf(bn_s[b * 4 + 1] * 60.0f), 0), GD - 1);
        int x2 = (int)ceilf(bn_s[b * 4 + 2] * 60.0f);
        int y2 = (int)ceilf(bn_s[b * 4 + 3] * 60.0f);
        x2 = min(max(x2, x1 + 1), GD);
        y2 = min(max(y2, y1 + 1), GD);
        int wd = x2 - x1;
        int area = wd * (y2 - y1);
        float s0 = 0.f, s1 = 0.f, q0 = 0.f, q1 = 0.f;
        float mx0 = -1e30f, mx1 = -1e30f, mn0 = 1e30f, mn1 = 1e30f;
        for (int c = lane; c < area; c += 32) {
            int ry = c / wd;
            int idx = (y1 + ry) * GD + x1 + (c - ry * wd);
            float v0 = wbuf[idx];
            float v1 = wbuf[GG + idx];
            s0 += v0; q0 += v0 * v0; mx0 = fmaxf(mx0, v0); mn0 = fminf(mn0, v0);
            s1 += v1; q1 += v1 * v1; mx1 = fmaxf(mx1, v1); mn1 = fminf(mn1, v1);
        }
        #pragma unroll
        for (int o = 16; o; o >>= 1) {
            s0 += __shfl_xor_sync(0xffffffffu, s0, o);
            s1 += __shfl_xor_sync(0xffffffffu, s1, o);
            q0 += __shfl_xor_sync(0xffffffffu, q0, o);
            q1 += __shfl_xor_sync(0xffffffffu, q1, o);
            mx0 = fmaxf(mx0, __shfl_xor_sync(0xffffffffu, mx0, o));
            mx1 = fmaxf(mx1, __shfl_xor_sync(0xffffffffu, mx1, o));
            mn0 = fminf(mn0, __shfl_xor_sync(0xffffffffu, mn0, o));
            mn1 = fminf(mn1, __shfl_xor_sync(0xffffffffu, mn1, o));
        }
        if (lane == 0) {
            float cnt = (float)area;
            float m0 = s0 / cnt, m1 = s1 / cnt;
            float v0 = q0 / cnt - m0 * m0;
            float v1 = q1 / cnt - m1 * m1;
            stats_s[b * 6 + 0] = m0;
            stats_s[b * 6 + 1] = m1;
            stats_s[b * 6 + 2] = sqrtf(fmaxf(v0, 0.0f));
            stats_s[b * 6 + 3] = sqrtf(fmaxf(v1, 0.0f));
            stats_s[b * 6 + 4] = mx0 - mn0;
            stats_s[b * 6 + 5] = mx1 - mn1;
        }
    }
    __syncthreads();

    // ---------------- Phase A2: z_mv = stats@W_stats.T + b ; z1 = bn@W_b1.T + b ----------------
    for (int idx = tid; idx < TB * 64; idx += NTHREADS) {
        int b = idx >> 6, j = idx & 63;
        const float* wr = p.W_stats + j * 6;
        const float* st = stats_s + b * 6;
        float z = p.b_stats[j];
        #pragma unroll
        for (int k = 0; k < 6; k++) z = fmaf(st[k], wr[k], z);
        zA[idx] = z;
    }
    for (int idx = tid; idx < TB * 32; idx += NTHREADS) {
        int b = idx >> 5, j = idx & 31;
        const float* wr = p.W_b1 + j * 4;
        const float* bn = bn_s + b * 4;
        float z = p.b_b1[j];
        #pragma unroll
        for (int k = 0; k < 4; k++) z = fmaf(bn[k], wr[k], z);
        zB[idx] = z;
    }
    __syncthreads();

    // ---------------- Phase A3: LN(z_mv) -> x[:,0:64] ; LN(z1) -> h1 ----------------
    for (int bb = 0; bb < 4; bb++) {
        int b = 4 * w + bb;
        float v0 = zA[b * 64 + lane];
        float v1 = zA[b * 64 + 32 + lane];
        float s = v0 + v1, q = v0 * v0 + v1 * v1;
        float u = zB[b * 32 + lane];
        float s2 = u, q2 = u * u;
        #pragma unroll
        for (int o = 16; o; o >>= 1) {
            s  += __shfl_xor_sync(0xffffffffu, s, o);
            q  += __shfl_xor_sync(0xffffffffu, q, o);
            s2 += __shfl_xor_sync(0xffffffffu, s2, o);
            q2 += __shfl_xor_sync(0xffffffffu, q2, o);
        }
        float mu = s * (1.0f / 64.0f);
        float var = fmaxf(q * (1.0f / 64.0f) - mu * mu, 0.0f);
        float inv = rsqrtf(var + 1e-5f);
        x_s[b * 96 + lane]      = fmaxf(fmaf((v0 - mu) * inv, p.g_stats[lane],      p.be_stats[lane]),      0.0f);
        x_s[b * 96 + 32 + lane] = fmaxf(fmaf((v1 - mu) * inv, p.g_stats[lane + 32], p.be_stats[lane + 32]), 0.0f);
        float mu2 = s2 * (1.0f / 32.0f);
        float var2 = fmaxf(q2 * (1.0f / 32.0f) - mu2 * mu2, 0.0f);
        float inv2 = rsqrtf(var2 + 1e-5f);
        h1_s[b * 32 + lane] = fmaxf(fmaf((u - mu2) * inv2, p.g_b1[lane], p.be_b1[lane]), 0.0f);
    }
    __syncthreads();

    // ---------------- Phase A4: z2 = h1@W_b2.T + b ----------------
    for (int idx = tid; idx < TB * 32; idx += NTHREADS) {
        int b = idx >> 5, j = idx & 31;
        const float* wr = p.W_b2 + j * 32;
        const float* hh = h1_s + b * 32;
        float z = p.b_b2[j];
        #pragma unroll
        for (int k = 0; k < 32; k++) z = fmaf(hh[k], wr[k], z);
        zB[idx] = z;
    }
    __syncthreads();

    // ---------------- Phase A5: LN(z2) -> x[:,64:96] ----------------
    for (int bb = 0; bb < 4; bb++) {
        int b = 4 * w + bb;
        float u = zB[b * 32 + lane];
        float s = u, q = u * u;
        #pragma unroll
        for (int o = 16; o; o >>= 1) {
            s += __shfl_xor_sync(0xffffffffu, s, o);
            q += __shfl_xor_sync(0xffffffffu, q, o);
        }
        float mu = s * (1.0f / 32.0f);
        float var = fmaxf(q * (1.0f / 32.0f) - mu * mu, 0.0f);
        float inv = rsqrtf(var + 1e-5f);
        x_s[b * 96 + 64 + lane] = fmaxf(fmaf((u - mu) * inv, p.g_b2[lane], p.be_b2[lane]), 0.0f);
    }
    __syncthreads();

    // ---------------- Phase B1: gates GEMM  (skip f gate: 384 rows) ----------------
    // warp w -> boxes 4w..4w+3; lane l -> gate columns l+32j, j<12
    // gate remap: n<128 -> i (row n), 128<=n<256 -> g (row n+128), 256<=n<384 -> o (row n+128)
    float acc[4][12];
    #pragma unroll
    for (int m = 0; m < 4; m++)
        #pragma unroll
        for (int j = 0; j < 12; j++) acc[m][j] = 0.0f;

    for (int kc = 0; kc < 96; kc += 16) {
        for (int e = tid; e < 384 * 16; e += NTHREADS) {
            int n = e >> 4, k = e & 15;
            int row = (n < 128) ? n : n + 128;
            wbuf[n * 17 + k] = p.W_ih[row * 96 + kc + k];
        }
        __syncthreads();
        #pragma unroll
        for (int k = 0; k < 16; k++) {
            float xv[4];
            #pragma unroll
            for (int m = 0; m < 4; m++) xv[m] = x_s[(4 * w + m) * 96 + kc + k];
            #pragma unroll
            for (int j = 0; j < 12; j++) {
                float wv = wbuf[(lane + 32 * j) * 17 + k];
                #pragma unroll
                for (int m = 0; m < 4; m++) acc[m][j] = fmaf(xv[m], wv, acc[m][j]);
            }
        }
        __syncthreads();
    }
    #pragma unroll
    for (int j = 0; j < 12; j++) {
        int n = lane + 32 * j;
        int row = (n < 128) ? n : n + 128;
        float bias = p.b_ih[row] + p.b_hh[row];
        #pragma unroll
        for (int m = 0; m < 4; m++)
            gates_s[(4 * w + m) * 384 + n] = acc[m][j] + bias;
    }
    __syncthreads();

    // ---------------- Phase B2: LSTM elementwise (c0=0) ----------------
    for (int idx = tid; idx < TB * 128; idx += NTHREADS) {
        int b = idx >> 7, hh = idx & 127;
        float iv = gates_s[b * 384 + hh];
        float gv = gates_s[b * 384 + 128 + hh];
        float ov = gates_s[b * 384 + 256 + hh];
        float c = sigmoidf_(iv) * tanhf(gv);
        h_s[b * 128 + hh] = sigmoidf_(ov) * tanhf(c);
    }
    __syncthreads();

    // ---------------- Phase B3: heads GEMM (192 outputs: p|s|c hidden) ----------------
    float acc2[4][6];
    #pragma unroll
    for (int m = 0; m < 4; m++)
        #pragma unroll
        for (int j = 0; j < 6; j++) acc2[m][j] = 0.0f;

    for (int kc = 0; kc < 128; kc += 32) {
        for (int e = tid; e < 192 * 32; e += NTHREADS) {
            int n = e >> 5, k = e & 31;
            const float* src = (n < 64) ? (p.W_p1 + n * 128)
                             : (n < 128) ? (p.W_s1 + (n - 64) * 128)
                                         : (p.W_c1 + (n - 128) * 128);
            wbuf[n * 33 + k] = src[kc + k];
        }
        __syncthreads();
        #pragma unroll
        for (int k = 0; k < 32; k++) {
            float hv[4];
            #pragma unroll
            for (int m = 0; m < 4; m++) hv[m] = h_s[(4 * w + m) * 128 + kc + k];
            #pragma unroll
            for (int j = 0; j < 6; j++) {
                float wv = wbuf[(lane + 32 * j) * 33 + k];
                #pragma unroll
                for (int m = 0; m < 4; m++) acc2[m][j] = fmaf(hv[m], wv, acc2[m][j]);
            }
        }
        __syncthreads();
    }
    #pragma unroll
    for (int j = 0; j < 6; j++) {
        int n = lane + 32 * j;
        float bias = (n < 64) ? p.b_p1[n] : (n < 128) ? p.b_s1[n - 64] : p.b_c1[n - 128];
        #pragma unroll
        for (int m = 0; m < 4; m++)
            hid_s[(4 * w + m) * 192 + n] = fmaxf(acc2[m][j] + bias, 0.0f);
    }
    __syncthreads();

    // ---------------- Phase B4: head second layers ----------------
    if (tid < TB * 5) {
        int b = tid / 5, o = tid % 5;
        const float* hp = hid_s + b * 192 + ((o < 2) ? 0 : (o < 4) ? 64 : 128);
        const float* wp;
        float bias;
        if (o == 0)      { wp = p.W_p2;      bias = p.b_p2[0]; }
        else if (o == 1) { wp = p.W_p2 + 64; bias = p.b_p2[1]; }
        else if (o == 2) { wp = p.W_s2;      bias = p.b_s2[0]; }
        else if (o == 3) { wp = p.W_s2 + 64; bias = p.b_s2[1]; }
        else             { wp = p.W_c2;      bias = p.b_c2[0]; }
        float a = bias;
        #pragma unroll
        for (int k = 0; k < 64; k++) a = fmaf(hp[k], wp[k], a);
        fin_s[b * 5 + o] = a;
    }
    __syncthreads();

    // ---------------- Phase B5: box decode + output ----------------
    if (tid < TB) {
        int b = tid;
        const float* bx = p.boxes + (box0 + b) * 4;
        float X1 = bx[0], Y1 = bx[1], X2 = bx[2], Y2 = bx[3];
        float cx = (X1 + X2) * 0.5f, cy = (Y1 + Y2) * 0.5f;
        float wd = X2 - X1, hg = Y2 - Y1;
        float ncx = cx + fin_s[b * 5 + 0];
        float ncy = cy + fin_s[b * 5 + 1];
        float nw = wd * expf(fin_s[b * 5 + 2]);
        float nh = hg * expf(fin_s[b * 5 + 3]);
        float conf = sigmoidf_(fin_s[b * 5 + 4]);
        float* op = p.out + (box0 + b) * 5;
        op[0] = ncx - nw * 0.5f;
        op[1] = ncy - nh * 0.5f;
        op[2] = ncx + nw * 0.5f;
        op[3] = ncy + nh * 0.5f;
        op[4] = conf;
    }
}

extern "C" void kernel_launch(void* const* d_in, const int* in_sizes, int n_in,
                              void* d_out, int out_size) {
    (void)in_sizes; (void)n_in; (void)out_size;
    Params p;
    p.mv       = (const float*)d_in[0];
    p.boxes    = (const float*)d_in[1];
    p.W_stats  = (const float*)d_in[2];
    p.b_stats  = (const float*)d_in[3];
    p.g_stats  = (const float*)d_in[4];
    p.be_stats = (const float*)d_in[5];
    p.W_b1     = (const float*)d_in[6];
    p.b_b1     = (const float*)d_in[7];
    p.g_b1     = (const float*)d_in[8];
    p.be_b1    = (const float*)d_in[9];
    p.W_b2     = (const float*)d_in[10];
    p.b_b2     = (const float*)d_in[11];
    p.g_b2     = (const float*)d_in[12];
    p.be_b2    = (const float*)d_in[13];
    p.W_ih     = (const float*)d_in[14];
    p.W_hh     = (const float*)d_in[15];
    p.b_ih     = (const float*)d_in[16];
    p.b_hh     = (const float*)d_in[17];
    p.W_p1     = (const float*)d_in[18];
    p.b_p1     = (const float*)d_in[19];
    p.W_p2     = (const float*)d_in[20];
    p.b_p2     = (const float*)d_in[21];
    p.W_s1     = (const float*)d_in[22];
    p.b_s1     = (const float*)d_in[23];
    p.W_s2     = (const float*)d_in[24];
    p.b_s2     = (const float*)d_in[25];
    p.W_c1     = (const float*)d_in[26];
    p.b_c1     = (const float*)d_in[27];
    p.W_c2     = (const float*)d_in[28];
    p.b_c2     = (const float*)d_in[29];
    p.out      = (float*)d_out;

    cudaFuncSetAttribute(tracker_fused_kernel,
                         cudaFuncAttributeMaxDynamicSharedMemorySize, SMEM_BYTES);
    tracker_fused_kernel<<<4096 / TB, NTHREADS, SMEM_BYTES>>>(p);
}

// round 2
// speedup vs baseline: 1.7115x; 1.7115x over previous
#include <cuda_runtime.h>
#include <math.h>

#define GD 60
#define GG 3600
#define NT 512

// shared memory layout (floats)
//   x_s  @ 0      : 32*96          = 3072
//   wbuf @ 3072   : 384*100        = 38400   (gates W tile; later 192*132=25344 heads tile)
//   big  @ 41472  : 10400
// total 51872 floats = 207488 bytes
#define XS_OFF 0
#define WB_OFF 3072
#define BIG_OFF 41472
#define SMEM_BYTES (51872 * 4)

struct Params {
    const float* mv;
    const float* boxes;
    const float* W_stats; const float* b_stats; const float* g_stats; const float* be_stats;
    const float* W_b1;    const float* b_b1;    const float* g_b1;    const float* be_b1;
    const float* W_b2;    const float* b_b2;    const float* g_b2;    const float* be_b2;
    const float* W_ih;    const float* W_hh;    const float* b_ih;    const float* b_hh;
    const float* W_p1;    const float* b_p1;    const float* W_p2;    const float* b_p2;
    const float* W_s1;    const float* b_s1;    const float* W_s2;    const float* b_s2;
    const float* W_c1;    const float* b_c1;    const float* W_c2;    const float* b_c2;
    float* out;
};

__device__ __forceinline__ float sigmoidf_(float x) {
    return 1.0f / (1.0f + expf(-x));
}

__device__ __forceinline__ void cp16(float* dst, const float* src) {
    unsigned saddr = (unsigned)__cvta_generic_to_shared(dst);
    asm volatile("cp.async.cg.shared.global [%0], [%1], 16;" :: "r"(saddr), "l"(src));
}

__global__ void __launch_bounds__(NT, 1)
tracker_fused_kernel(Params p) {
    extern __shared__ float smem[];
    float* x_s  = smem + XS_OFF;    // [32][96]
    float* wbuf = smem + WB_OFF;
    float* big  = smem + BIG_OFF;

    // phase-A views
    float* stats_s = big;           // 192
    float* bn_s    = big + 192;     // 128
    float* zA      = big + 320;     // 2048 [32][64]
    float* zB      = big + 2368;    // 1024 [32][32]
    float* h1_s    = big + 3392;    // 1024 [32][32]
    // phase-B views (phase-A data dead by first use)
    float* h_s   = big;             // [32][128] = 4096
    float* hid_s = big + 4096;      // [32][192] = 6144
    float* fin_s = big + 10240;     // 160

    const int tid  = threadIdx.x;
    const int lane = tid & 31;
    const int w    = tid >> 5;      // 0..15
    const int half = w >> 3;        // 0/1
    const int wq   = w & 7;         // 0..7 -> boxes 4wq..4wq+3
    const int box0 = blockIdx.x * 32;

    // ============ Prefetch W_ih tile (f-gate skipped) via cp.async ============
    // 384 rows x 96 floats -> wbuf[n*100 + k], 9216 float4, 18 per thread
    #pragma unroll
    for (int it = 0; it < 18; it++) {
        int idx = tid + it * NT;
        int n = idx / 24, k4 = idx % 24;
        int row = (n < 128) ? n : n + 128;     // skip f rows 128..255
        cp16(wbuf + n * 100 + 4 * k4, p.W_ih + row * 96 + 4 * k4);
    }
    asm volatile("cp.async.commit_group;");

    // ============ Phase A0: boxes_norm ============
    if (tid < 128) {
        int b = tid >> 2, c = tid & 3;
        float v = p.boxes[(box0 + b) * 4 + c] * (1.0f / 960.0f);
        bn_s[b * 4 + c] = fminf(fmaxf(v, 0.0f), 1.0f);
    }
    __syncthreads();

    // ============ Phase A1: box-motion stats (warp per 2 boxes, mv via L1) ============
    for (int bb = 0; bb < 2; bb++) {
        int b = w * 2 + bb;
        int x1 = min(max((int)floorf(bn_s[b * 4 + 0] * 60.0f), 0), GD - 1);
        int y1 = min(max((int)floorf(bn_s[b * 4 + 1] * 60.0f), 0), GD - 1);
        int x2 = (int)ceilf(bn_s[b * 4 + 2] * 60.0f);
        int y2 = (int)ceilf(bn_s[b * 4 + 3] * 60.0f);
        x2 = min(max(x2, x1 + 1), GD);
        y2 = min(max(y2, y1 + 1), GD);
        int wd = x2 - x1;
        int area = wd * (y2 - y1);
        float s0 = 0.f, s1 = 0.f, q0 = 0.f, q1 = 0.f;
        float mx0 = -1e30f, mx1 = -1e30f, mn0 = 1e30f, mn1 = 1e30f;
        for (int c = lane; c < area; c += 32) {
            int ry = c / wd;
            int idx = (y1 + ry) * GD + x1 + (c - ry * wd);
            float v0 = __ldg(p.mv + idx);
            float v1 = __ldg(p.mv + GG + idx);
            s0 += v0; q0 += v0 * v0; mx0 = fmaxf(mx0, v0); mn0 = fminf(mn0, v0);
            s1 += v1; q1 += v1 * v1; mx1 = fmaxf(mx1, v1); mn1 = fminf(mn1, v1);
        }
        #pragma unroll
        for (int o = 16; o; o >>= 1) {
            s0 += __shfl_xor_sync(0xffffffffu, s0, o);
            s1 += __shfl_xor_sync(0xffffffffu, s1, o);
            q0 += __shfl_xor_sync(0xffffffffu, q0, o);
            q1 += __shfl_xor_sync(0xffffffffu, q1, o);
            mx0 = fmaxf(mx0, __shfl_xor_sync(0xffffffffu, mx0, o));
            mx1 = fmaxf(mx1, __shfl_xor_sync(0xffffffffu, mx1, o));
            mn0 = fminf(mn0, __shfl_xor_sync(0xffffffffu, mn0, o));
            mn1 = fminf(mn1, __shfl_xor_sync(0xffffffffu, mn1, o));
        }
        if (lane == 0) {
            float cnt = (float)area;
            float m0 = s0 / cnt, m1 = s1 / cnt;
            float v0 = q0 / cnt - m0 * m0;
            float v1 = q1 / cnt - m1 * m1;
            stats_s[b * 6 + 0] = m0;
            stats_s[b * 6 + 1] = m1;
            stats_s[b * 6 + 2] = sqrtf(fmaxf(v0, 0.0f));
            stats_s[b * 6 + 3] = sqrtf(fmaxf(v1, 0.0f));
            stats_s[b * 6 + 4] = mx0 - mn0;
            stats_s[b * 6 + 5] = mx1 - mn1;
        }
    }
    __syncthreads();

    // ============ Phase A2: z_mv = stats@Ws.T + b ; z1 = bn@Wb1.T + b ============
    #pragma unroll
    for (int it = 0; it < 4; it++) {
        int idx = tid + it * NT;              // 2048
        int b = idx >> 6, j = idx & 63;
        const float* wr = p.W_stats + j * 6;
        const float* st = stats_s + b * 6;
        float z = p.b_stats[j];
        #pragma unroll
        for (int k = 0; k < 6; k++) z = fmaf(st[k], wr[k], z);
        zA[idx] = z;
    }
    #pragma unroll
    for (int it = 0; it < 2; it++) {
        int idx = tid + it * NT;              // 1024
        int b = idx >> 5, j = idx & 31;
        const float* wr = p.W_b1 + j * 4;
        const float* bn = bn_s + b * 4;
        float z = p.b_b1[j];
        #pragma unroll
        for (int k = 0; k < 4; k++) z = fmaf(bn[k], wr[k], z);
        zB[idx] = z;
    }
    __syncthreads();

    // ============ Phase A3: LN(z_mv) -> x[:,0:64] ; LN(z1) -> h1 ============
    for (int bb = 0; bb < 2; bb++) {
        int b = 2 * w + bb;
        float v0 = zA[b * 64 + lane];
        float v1 = zA[b * 64 + 32 + lane];
        float s = v0 + v1, q = v0 * v0 + v1 * v1;
        float u = zB[b * 32 + lane];
        float s2 = u, q2 = u * u;
        #pragma unroll
        for (int o = 16; o; o >>= 1) {
            s  += __shfl_xor_sync(0xffffffffu, s, o);
            q  += __shfl_xor_sync(0xffffffffu, q, o);
            s2 += __shfl_xor_sync(0xffffffffu, s2, o);
            q2 += __shfl_xor_sync(0xffffffffu, q2, o);
        }
        float mu = s * (1.0f / 64.0f);
        float var = fmaxf(q * (1.0f / 64.0f) - mu * mu, 0.0f);
        float inv = rsqrtf(var + 1e-5f);
        x_s[b * 96 + lane]      = fmaxf(fmaf((v0 - mu) * inv, p.g_stats[lane],      p.be_stats[lane]),      0.0f);
        x_s[b * 96 + 32 + lane] = fmaxf(fmaf((v1 - mu) * inv, p.g_stats[lane + 32], p.be_stats[lane + 32]), 0.0f);
        float mu2 = s2 * (1.0f / 32.0f);
        float var2 = fmaxf(q2 * (1.0f / 32.0f) - mu2 * mu2, 0.0f);
        float inv2 = rsqrtf(var2 + 1e-5f);
        h1_s[b * 32 + lane] = fmaxf(fmaf((u - mu2) * inv2, p.g_b1[lane], p.be_b1[lane]), 0.0f);
    }
    __syncthreads();

    // ============ Phase A4: z2 = h1@Wb2.T + b ============
    #pragma unroll
    for (int it = 0; it < 2; it++) {
        int idx = tid + it * NT;
        int b = idx >> 5, j = idx & 31;
        const float* wr = p.W_b2 + j * 32;
        const float* hh = h1_s + b * 32;
        float z = p.b_b2[j];
        #pragma unroll
        for (int k = 0; k < 32; k++) z = fmaf(hh[k], wr[k], z);
        zB[idx] = z;
    }
    __syncthreads();

    // ============ Phase A5: LN(z2) -> x[:,64:96] ============
    for (int bb = 0; bb < 2; bb++) {
        int b = 2 * w + bb;
        float u = zB[b * 32 + lane];
        float s = u, q = u * u;
        #pragma unroll
        for (int o = 16; o; o >>= 1) {
            s += __shfl_xor_sync(0xffffffffu, s, o);
            q += __shfl_xor_sync(0xffffffffu, q, o);
        }
        float mu = s * (1.0f / 32.0f);
        float var = fmaxf(q * (1.0f / 32.0f) - mu * mu, 0.0f);
        float inv = rsqrtf(var + 1e-5f);
        x_s[b * 96 + 64 + lane] = fmaxf(fmaf((u - mu) * inv, p.g_b2[lane], p.be_b2[lane]), 0.0f);
    }

    // gates weights must be in smem before GEMM
    asm volatile("cp.async.wait_group 0;");
    __syncthreads();

    // ============ Phase B1: gates GEMM ============
    // warp (half, wq): boxes 4wq..4wq+3, cols n = lane + 32*j, j = 2*half + (u&1) + 4*(u>>1)
    // u=0,1 -> i gate; u=2,3 -> g gate; u=4,5 -> o gate, hidden unit hu = lane+32*(2*half+(u&1))
    float acc[4][6];
    #pragma unroll
    for (int m = 0; m < 4; m++)
        #pragma unroll
        for (int u = 0; u < 6; u++) acc[m][u] = 0.0f;

    int wrow[6];
    #pragma unroll
    for (int u = 0; u < 6; u++) {
        int j = 2 * half + (u & 1) + 4 * (u >> 1);
        wrow[u] = (lane + 32 * j) * 100;
    }
    const float* xb = x_s + 4 * wq * 96;

    #pragma unroll 4
    for (int k4 = 0; k4 < 24; k4++) {
        float4 xv[4];
        #pragma unroll
        for (int m = 0; m < 4; m++) xv[m] = *(const float4*)(xb + m * 96 + 4 * k4);
        #pragma unroll
        for (int u = 0; u < 6; u++) {
            float4 wv = *(const float4*)(wbuf + wrow[u] + 4 * k4);
            #pragma unroll
            for (int m = 0; m < 4; m++) {
                acc[m][u] = fmaf(xv[m].x, wv.x, acc[m][u]);
                acc[m][u] = fmaf(xv[m].y, wv.y, acc[m][u]);
                acc[m][u] = fmaf(xv[m].z, wv.z, acc[m][u]);
                acc[m][u] = fmaf(xv[m].w, wv.w, acc[m][u]);
            }
        }
    }

    float biasv[6];
    #pragma unroll
    for (int u = 0; u < 6; u++) {
        int j = 2 * half + (u & 1) + 4 * (u >> 1);
        int n = lane + 32 * j;
        int r = (j < 4) ? n : n + 128;
        biasv[u] = p.b_ih[r] + p.b_hh[r];
    }

    __syncthreads();  // all wbuf reads done before heads restage

    // ============ Prefetch heads weights (overlap with LSTM) ============
    // 192 rows x 128 floats -> wbuf[n*132 + k], 6144 float4, 12 per thread
    #pragma unroll
    for (int it = 0; it < 12; it++) {
        int idx = tid + it * NT;
        int n = idx >> 5, k4 = idx & 31;
        const float* src = (n < 64) ? (p.W_p1 + n * 128)
                         : (n < 128) ? (p.W_s1 + (n - 64) * 128)
                                     : (p.W_c1 + (n - 128) * 128);
        cp16(wbuf + n * 132 + 4 * k4, src + 4 * k4);
    }
    asm volatile("cp.async.commit_group;");

    // ============ Phase B2: LSTM in registers (h0=c0=0) ============
    #pragma unroll
    for (int m = 0; m < 4; m++) {
        #pragma unroll
        for (int t = 0; t < 2; t++) {
            float iv = acc[m][t]     + biasv[t];
            float gv = acc[m][2 + t] + biasv[2 + t];
            float ov = acc[m][4 + t] + biasv[4 + t];
            float c = sigmoidf_(iv) * tanhf(gv);
            h_s[(4 * wq + m) * 128 + lane + 32 * (2 * half + t)] = sigmoidf_(ov) * tanhf(c);
        }
    }

    asm volatile("cp.async.wait_group 0;");
    __syncthreads();

    // ============ Phase B3: heads GEMM (192 cols: p1|s1|c1 hidden) ============
    float acc2[4][3];
    #pragma unroll
    for (int m = 0; m < 4; m++)
        #pragma unroll
        for (int u = 0; u < 3; u++) acc2[m][u] = 0.0f;

    int wrow2[3];
    #pragma unroll
    for (int u = 0; u < 3; u++) wrow2[u] = (lane + 32 * (3 * half + u)) * 132;
    const float* hb = h_s + 4 * wq * 128;

    #pragma unroll 4
    for (int k4 = 0; k4 < 32; k4++) {
        float4 hv[4];
        #pragma unroll
        for (int m = 0; m < 4; m++) hv[m] = *(const float4*)(hb + m * 128 + 4 * k4);
        #pragma unroll
        for (int u = 0; u < 3; u++) {
            float4 wv = *(const float4*)(wbuf + wrow2[u] + 4 * k4);
            #pragma unroll
            for (int m = 0; m < 4; m++) {
                acc2[m][u] = fmaf(hv[m].x, wv.x, acc2[m][u]);
                acc2[m][u] = fmaf(hv[m].y, wv.y, acc2[m][u]);
                acc2[m][u] = fmaf(hv[m].z, wv.z, acc2[m][u]);
                acc2[m][u] = fmaf(hv[m].w, wv.w, acc2[m][u]);
            }
        }
    }
    #pragma unroll
    for (int u = 0; u < 3; u++) {
        int n = lane + 32 * (3 * half + u);
        float bias = (n < 64) ? p.b_p1[n] : (n < 128) ? p.b_s1[n - 64] : p.b_c1[n - 128];
        #pragma unroll
        for (int m = 0; m < 4; m++)
            hid_s[(4 * wq + m) * 192 + n] = fmaxf(acc2[m][u] + bias, 0.0f);
    }
    __syncthreads();

    // ============ Phase B4: head second layers (5 scalars per box) ============
    if (tid < 160) {
        int b = tid / 5, o = tid % 5;
        const float* hp = hid_s + b * 192 + ((o < 2) ? 0 : (o < 4) ? 64 : 128);
        const float* wp;
        float a;
        if (o == 0)      { wp = p.W_p2;      a = p.b_p2[0]; }
        else if (o == 1) { wp = p.W_p2 + 64; a = p.b_p2[1]; }
        else if (o == 2) { wp = p.W_s2;      a = p.b_s2[0]; }
        else if (o == 3) { wp = p.W_s2 + 64; a = p.b_s2[1]; }
        else             { wp = p.W_c2;      a = p.b_c2[0]; }
        #pragma unroll
        for (int k4 = 0; k4 < 16; k4++) {
            float4 hv = *(const float4*)(hp + 4 * k4);
            float4 wv = *(const float4*)(wp + 4 * k4);
            a = fmaf(hv.x, wv.x, a);
            a = fmaf(hv.y, wv.y, a);
            a = fmaf(hv.z, wv.z, a);
            a = fmaf(hv.w, wv.w, a);
        }
        fin_s[b * 5 + o] = a;
    }
    __syncthreads();

    // ============ Phase B5: box decode + output ============
    if (tid < 32) {
        int b = tid;
        const float* bx = p.boxes + (box0 + b) * 4;
        float X1 = bx[0], Y1 = bx[1], X2 = bx[2], Y2 = bx[3];
        float cx = (X1 + X2) * 0.5f, cy = (Y1 + Y2) * 0.5f;
        float wd = X2 - X1, hg = Y2 - Y1;
        float ncx = cx + fin_s[b * 5 + 0];
        float ncy = cy + fin_s[b * 5 + 1];
        float nw = wd * expf(fin_s[b * 5 + 2]);
        float nh = hg * expf(fin_s[b * 5 + 3]);
        float conf = sigmoidf_(fin_s[b * 5 + 4]);
        float* op = p.out + (box0 + b) * 5;
        op[0] = ncx - nw * 0.5f;
        op[1] = ncy - nh * 0.5f;
        op[2] = ncx + nw * 0.5f;
        op[3] = ncy + nh * 0.5f;
        op[4] = conf;
    }
}

extern "C" void kernel_launch(void* const* d_in, const int* in_sizes, int n_in,
                              void* d_out, int out_size) {
    (void)in_sizes; (void)n_in; (void)out_size;
    Params p;
    p.mv       = (const float*)d_in[0];
    p.boxes    = (const float*)d_in[1];
    p.W_stats  = (const float*)d_in[2];
    p.b_stats  = (const float*)d_in[3];
    p.g_stats  = (const float*)d_in[4];
    p.be_stats = (const float*)d_in[5];
    p.W_b1     = (const float*)d_in[6];
    p.b_b1     = (const float*)d_in[7];
    p.g_b1     = (const float*)d_in[8];
    p.be_b1    = (const float*)d_in[9];
    p.W_b2     = (const float*)d_in[10];
    p.b_b2     = (const float*)d_in[11];
    p.g_b2     = (const float*)d_in[12];
    p.be_b2    = (const float*)d_in[13];
    p.W_ih     = (const float*)d_in[14];
    p.W_hh     = (const float*)d_in[15];
    p.b_ih     = (const float*)d_in[16];
    p.b_hh     = (const float*)d_in[17];
    p.W_p1     = (const float*)d_in[18];
    p.b_p1     = (const float*)d_in[19];
    p.W_p2     = (const float*)d_in[20];
    p.b_p2     = (const float*)d_in[21];
    p.W_s1     = (const float*)d_in[22];
    p.b_s1     = (const float*)d_in[23];
    p.W_s2     = (const float*)d_in[24];
    p.b_s2     = (const float*)d_in[25];
    p.W_c1     = (const float*)d_in[26];
    p.b_c1     = (const float*)d_in[27];
    p.W_c2     = (const float*)d_in[28];
    p.b_c2     = (const float*)d_in[29];
    p.out      = (float*)d_out;

    cudaFuncSetAttribute(tracker_fused_kernel,
                         cudaFuncAttributeMaxDynamicSharedMemorySize, SMEM_BYTES);
    tracker_fused_kernel<<<128, NT, SMEM_BYTES>>>(p);
}

// round 3
// speedup vs baseline: 1.9221x; 1.1231x over previous
#include <cuda_runtime.h>
#include <math.h>

#define GD 60
#define GG 3600
#define NT 512

// shared memory layout (floats)
//   x_s  @ 0      : 32*96  = 3072
//   wbuf @ 3072   : 38400  (gates tile 384*100=38400 ; heads tile 192*132=25344 ; scratch @ +25600 : 6144)
//   big  @ 41472  : 10400  (phase A: hwarp[32][32] ; phase B: h_s[32][128] | hid_s[32][192] | fin[160])
#define XS_OFF  0
#define WB_OFF  3072
#define BIG_OFF 41472
#define SCR_OFF (WB_OFF + 25600)
#define SMEM_BYTES (51872 * 4)

struct Params {
    const float* mv;
    const float* boxes;
    const float* W_stats; const float* b_stats; const float* g_stats; const float* be_stats;
    const float* W_b1;    const float* b_b1;    const float* g_b1;    const float* be_b1;
    const float* W_b2;    const float* b_b2;    const float* g_b2;    const float* be_b2;
    const float* W_ih;    const float* W_hh;    const float* b_ih;    const float* b_hh;
    const float* W_p1;    const float* b_p1;    const float* W_p2;    const float* b_p2;
    const float* W_s1;    const float* b_s1;    const float* W_s2;    const float* b_s2;
    const float* W_c1;    const float* b_c1;    const float* W_c2;    const float* b_c2;
    float* out;
};

__device__ __forceinline__ float sig_(float x) {
    return __fdividef(1.0f, 1.0f + __expf(-x));
}
__device__ __forceinline__ float tanh_(float x) {
    return fmaf(2.0f, sig_(2.0f * x), -1.0f);
}

union F4 { float4 f; unsigned long long u2[2]; };

__device__ __forceinline__ void ffma2(unsigned long long& d,
                                      const unsigned long long a,
                                      const unsigned long long b) {
    asm("fma.rn.f32x2 %0, %1, %2, %0;" : "+l"(d) : "l"(a), "l"(b));
}
__device__ __forceinline__ float red2(unsigned long long v) {
    float lo, hi;
    asm("mov.b64 {%0, %1}, %2;" : "=f"(lo), "=f"(hi) : "l"(v));
    return lo + hi;
}

__device__ __forceinline__ void cp16(float* dst, const float* src) {
    unsigned saddr = (unsigned)__cvta_generic_to_shared(dst);
    asm volatile("cp.async.cg.shared.global [%0], [%1], 16;" :: "r"(saddr), "l"(src));
}

__global__ void __launch_bounds__(NT, 1)
tracker_fused_kernel(Params p) {
    extern __shared__ float smem[];
    float* x_s   = smem + XS_OFF;    // [32][96]
    float* wbuf  = smem + WB_OFF;
    float* big   = smem + BIG_OFF;
    float* scr   = smem + SCR_OFF;   // 6144 floats

    float* hwarp = big;              // phase A: [32][32]
    float* h_s   = big;              // phase B: [32][128]
    float* hid_s = big + 4096;       // [32][192]
    float* fin_s = big + 10240;      // 160

    const int tid  = threadIdx.x;
    const int lane = tid & 31;
    const int w    = tid >> 5;       // 0..15
    const int box0 = blockIdx.x * 32;

    // ============ Prefetch W_ih tile (f-gate skipped): group A ============
    // packed rows: n<128 -> i rows n ; 128..255 -> g rows n+128 ; 256..383 -> o rows n+128
    #pragma unroll
    for (int it = 0; it < 18; it++) {
        int idx = tid + it * NT;
        int n = idx / 24, k4 = idx % 24;
        int row = (n < 128) ? n : n + 128;
        cp16(wbuf + n * 100 + 4 * k4, p.W_ih + row * 96 + 4 * k4);
    }
    asm volatile("cp.async.commit_group;");

    // ============ Phase A: fully warp-local, 2 boxes per warp ============
    for (int bb = 0; bb < 2; bb++) {
        int b = 2 * w + bb;
        float4 bxr = __ldg((const float4*)p.boxes + (box0 + b));
        float bn0 = fminf(fmaxf(bxr.x * (1.0f / 960.0f), 0.0f), 1.0f);
        float bn1 = fminf(fmaxf(bxr.y * (1.0f / 960.0f), 0.0f), 1.0f);
        float bn2 = fminf(fmaxf(bxr.z * (1.0f / 960.0f), 0.0f), 1.0f);
        float bn3 = fminf(fmaxf(bxr.w * (1.0f / 960.0f), 0.0f), 1.0f);

        // --- rect motion stats ---
        int x1 = min(max((int)floorf(bn0 * 60.0f), 0), GD - 1);
        int y1 = min(max((int)floorf(bn1 * 60.0f), 0), GD - 1);
        int x2 = (int)ceilf(bn2 * 60.0f);
        int y2 = (int)ceilf(bn3 * 60.0f);
        x2 = min(max(x2, x1 + 1), GD);
        y2 = min(max(y2, y1 + 1), GD);
        int wd = x2 - x1;
        int area = wd * (y2 - y1);
        float s0 = 0.f, s1 = 0.f, q0 = 0.f, q1 = 0.f;
        float mx0 = -1e30f, mx1 = -1e30f, mn0 = 1e30f, mn1 = 1e30f;
        for (int c = lane; c < area; c += 32) {
            int ry = c / wd;
            int idx = (y1 + ry) * GD + x1 + (c - ry * wd);
            float v0 = __ldg(p.mv + idx);
            float v1 = __ldg(p.mv + GG + idx);
            s0 += v0; q0 += v0 * v0; mx0 = fmaxf(mx0, v0); mn0 = fminf(mn0, v0);
            s1 += v1; q1 += v1 * v1; mx1 = fmaxf(mx1, v1); mn1 = fminf(mn1, v1);
        }
        #pragma unroll
        for (int o = 16; o; o >>= 1) {
            s0 += __shfl_xor_sync(0xffffffffu, s0, o);
            s1 += __shfl_xor_sync(0xffffffffu, s1, o);
            q0 += __shfl_xor_sync(0xffffffffu, q0, o);
            q1 += __shfl_xor_sync(0xffffffffu, q1, o);
            mx0 = fmaxf(mx0, __shfl_xor_sync(0xffffffffu, mx0, o));
            mx1 = fmaxf(mx1, __shfl_xor_sync(0xffffffffu, mx1, o));
            mn0 = fminf(mn0, __shfl_xor_sync(0xffffffffu, mn0, o));
            mn1 = fminf(mn1, __shfl_xor_sync(0xffffffffu, mn1, o));
        }
        float rc = __fdividef(1.0f, (float)area);
        float m0 = s0 * rc, m1 = s1 * rc;
        float st[6];
        st[0] = m0;
        st[1] = m1;
        st[2] = sqrtf(fmaxf(q0 * rc - m0 * m0, 0.0f));
        st[3] = sqrtf(fmaxf(q1 * rc - m1 * m1, 0.0f));
        st[4] = mx0 - mn0;
        st[5] = mx1 - mn1;

        // --- z_mv: 2 cols per lane (lane, lane+32) ---
        float za = __ldg(p.b_stats + lane);
        float zb = __ldg(p.b_stats + lane + 32);
        const float* wsa = p.W_stats + lane * 6;
        const float* wsb = p.W_stats + (lane + 32) * 6;
        #pragma unroll
        for (int k = 0; k < 6; k++) {
            za = fmaf(st[k], __ldg(wsa + k), za);
            zb = fmaf(st[k], __ldg(wsb + k), zb);
        }
        // LN over 64
        {
            float s = za + zb, q = za * za + zb * zb;
            #pragma unroll
            for (int o = 16; o; o >>= 1) {
                s += __shfl_xor_sync(0xffffffffu, s, o);
                q += __shfl_xor_sync(0xffffffffu, q, o);
            }
            float mu = s * (1.0f / 64.0f);
            float var = fmaxf(q * (1.0f / 64.0f) - mu * mu, 0.0f);
            float inv = rsqrtf(var + 1e-5f);
            x_s[b * 96 + lane] =
                fmaxf(fmaf((za - mu) * inv, __ldg(p.g_stats + lane), __ldg(p.be_stats + lane)), 0.0f);
            x_s[b * 96 + 32 + lane] =
                fmaxf(fmaf((zb - mu) * inv, __ldg(p.g_stats + lane + 32), __ldg(p.be_stats + lane + 32)), 0.0f);
        }

        // --- box path: 4 -> 32 (LN,relu) -> 32 (LN,relu) ---
        float t = __ldg(p.b_b1 + lane);
        const float* wb1 = p.W_b1 + lane * 4;
        t = fmaf(bn0, __ldg(wb1 + 0), t);
        t = fmaf(bn1, __ldg(wb1 + 1), t);
        t = fmaf(bn2, __ldg(wb1 + 2), t);
        t = fmaf(bn3, __ldg(wb1 + 3), t);
        {
            float s = t, q = t * t;
            #pragma unroll
            for (int o = 16; o; o >>= 1) {
                s += __shfl_xor_sync(0xffffffffu, s, o);
                q += __shfl_xor_sync(0xffffffffu, q, o);
            }
            float mu = s * (1.0f / 32.0f);
            float var = fmaxf(q * (1.0f / 32.0f) - mu * mu, 0.0f);
            float inv = rsqrtf(var + 1e-5f);
            float h1 = fmaxf(fmaf((t - mu) * inv, __ldg(p.g_b1 + lane), __ldg(p.be_b1 + lane)), 0.0f);
            hwarp[b * 32 + lane] = h1;
        }
        __syncwarp();
        float t2 = __ldg(p.b_b2 + lane);
        const float* wb2 = p.W_b2 + lane * 32;
        #pragma unroll
        for (int k4 = 0; k4 < 8; k4++) {
            float4 wv = __ldg((const float4*)wb2 + k4);
            const float* hp = hwarp + b * 32 + 4 * k4;
            t2 = fmaf(hp[0], wv.x, t2);
            t2 = fmaf(hp[1], wv.y, t2);
            t2 = fmaf(hp[2], wv.z, t2);
            t2 = fmaf(hp[3], wv.w, t2);
        }
        __syncwarp();
        {
            float s = t2, q = t2 * t2;
            #pragma unroll
            for (int o = 16; o; o >>= 1) {
                s += __shfl_xor_sync(0xffffffffu, s, o);
                q += __shfl_xor_sync(0xffffffffu, q, o);
            }
            float mu = s * (1.0f / 32.0f);
            float var = fmaxf(q * (1.0f / 32.0f) - mu * mu, 0.0f);
            float inv = rsqrtf(var + 1e-5f);
            x_s[b * 96 + 64 + lane] =
                fmaxf(fmaf((t2 - mu) * inv, __ldg(p.g_b2 + lane), __ldg(p.be_b2 + lane)), 0.0f);
        }
    }

    asm volatile("cp.async.wait_group 0;");
    __syncthreads();   // x_s complete + W_ih staged

    // ============ Phase B1: gates GEMM (f32x2, k-paired) ============
    // warp: cg = w&3 (hidden-unit group), bg = w>>2 (8 boxes). Thread: hu = lane+32*cg,
    // cols = i/g/o of hidden unit hu for boxes 8bg..8bg+7.
    const int cg = w & 3;
    const int bg = w >> 2;
    const int hu = lane + 32 * cg;

    unsigned long long acc[8][3];
    #pragma unroll
    for (int m = 0; m < 8; m++)
        #pragma unroll
        for (int u = 0; u < 3; u++) acc[m][u] = 0ull;

    {
        const int wr0 = hu * 100;           // packed i row
        const int wr1 = (hu + 128) * 100;   // packed g row
        const int wr2 = (hu + 256) * 100;   // packed o row
        const float* xb = x_s + (8 * bg) * 96;

        #pragma unroll 4
        for (int k4 = 0; k4 < 24; k4++) {
            F4 wv0, wv1, wv2;
            wv0.f = *(const float4*)(wbuf + wr0 + 4 * k4);
            wv1.f = *(const float4*)(wbuf + wr1 + 4 * k4);
            wv2.f = *(const float4*)(wbuf + wr2 + 4 * k4);
            #pragma unroll
            for (int m = 0; m < 8; m++) {
                F4 xv;
                xv.f = *(const float4*)(xb + m * 96 + 4 * k4);
                ffma2(acc[m][0], xv.u2[0], wv0.u2[0]);
                ffma2(acc[m][0], xv.u2[1], wv0.u2[1]);
                ffma2(acc[m][1], xv.u2[0], wv1.u2[0]);
                ffma2(acc[m][1], xv.u2[1], wv1.u2[1]);
                ffma2(acc[m][2], xv.u2[0], wv2.u2[0]);
                ffma2(acc[m][2], xv.u2[1], wv2.u2[1]);
            }
        }
    }

    float bi = __ldg(p.b_ih + hu)       + __ldg(p.b_hh + hu);
    float bgv = __ldg(p.b_ih + 256 + hu) + __ldg(p.b_hh + 256 + hu);
    float bo = __ldg(p.b_ih + 384 + hu) + __ldg(p.b_hh + 384 + hu);

    __syncthreads();   // all wbuf reads done before heads restage

    // ============ Prefetch heads weights: group B ============
    #pragma unroll
    for (int it = 0; it < 12; it++) {
        int idx = tid + it * NT;
        int n = idx >> 5, k4 = idx & 31;
        const float* src = (n < 64) ? (p.W_p1 + n * 128)
                         : (n < 128) ? (p.W_s1 + (n - 64) * 128)
                                     : (p.W_c1 + (n - 128) * 128);
        cp16(wbuf + n * 132 + 4 * k4, src + 4 * k4);
    }
    asm volatile("cp.async.commit_group;");

    // ============ Phase B2: LSTM in registers (h0=c0=0) ============
    #pragma unroll
    for (int m = 0; m < 8; m++) {
        float iv = red2(acc[m][0]) + bi;
        float gv = red2(acc[m][1]) + bgv;
        float ov = red2(acc[m][2]) + bo;
        float c = sig_(iv) * tanh_(gv);
        h_s[(8 * bg + m) * 128 + hu] = sig_(ov) * tanh_(c);
    }

    asm volatile("cp.async.wait_group 0;");
    __syncthreads();   // h_s ready + heads weights staged

    // ============ Phase B3: heads GEMM (f32x2, k-split across warp halves) ============
    // kh = w>>3 (k-half), cg2 = (w&7)&1 (col group of 3), bg2 = (w&7)>>1 (8 boxes)
    const int kh  = w >> 3;
    const int cg2 = (w & 7) & 1;
    const int bg2 = (w & 7) >> 1;

    unsigned long long acc2[8][3];
    #pragma unroll
    for (int m = 0; m < 8; m++)
        #pragma unroll
        for (int u = 0; u < 3; u++) acc2[m][u] = 0ull;

    {
        int wr[3];
        #pragma unroll
        for (int u = 0; u < 3; u++) wr[u] = (lane + 32 * (3 * cg2 + u)) * 132;
        const float* hb = h_s + (8 * bg2) * 128;
        const int k40 = kh * 16;

        #pragma unroll 4
        for (int kk = 0; kk < 16; kk++) {
            int k4 = k40 + kk;
            F4 wv0, wv1, wv2;
            wv0.f = *(const float4*)(wbuf + wr[0] + 4 * k4);
            wv1.f = *(const float4*)(wbuf + wr[1] + 4 * k4);
            wv2.f = *(const float4*)(wbuf + wr[2] + 4 * k4);
            #pragma unroll
            for (int m = 0; m < 8; m++) {
                F4 hv;
                hv.f = *(const float4*)(hb + m * 128 + 4 * k4);
                ffma2(acc2[m][0], hv.u2[0], wv0.u2[0]);
                ffma2(acc2[m][0], hv.u2[1], wv0.u2[1]);
                ffma2(acc2[m][1], hv.u2[0], wv1.u2[0]);
                ffma2(acc2[m][1], hv.u2[1], wv1.u2[1]);
                ffma2(acc2[m][2], hv.u2[0], wv2.u2[0]);
                ffma2(acc2[m][2], hv.u2[1], wv2.u2[1]);
            }
        }
    }

    float ar[8][3];
    #pragma unroll
    for (int m = 0; m < 8; m++)
        #pragma unroll
        for (int u = 0; u < 3; u++) ar[m][u] = red2(acc2[m][u]);

    const int sbase = (((bg2 * 2 + cg2) * 32) + lane) * 24;
    if (kh == 1) {
        #pragma unroll
        for (int m = 0; m < 8; m++)
            #pragma unroll
            for (int u = 0; u < 3; u++) scr[sbase + m * 3 + u] = ar[m][u];
    }
    __syncthreads();
    if (kh == 0) {
        #pragma unroll
        for (int u = 0; u < 3; u++) {
            int n = lane + 32 * (3 * cg2 + u);
            float bias = (n < 64) ? __ldg(p.b_p1 + n)
                       : (n < 128) ? __ldg(p.b_s1 + n - 64)
                                   : __ldg(p.b_c1 + n - 128);
            #pragma unroll
            for (int m = 0; m < 8; m++)
                hid_s[(8 * bg2 + m) * 192 + n] =
                    fmaxf(ar[m][u] + scr[sbase + m * 3 + u] + bias, 0.0f);
        }
    }
    __syncthreads();

    // ============ Phase B4: head second layers (5 scalars per box) ============
    if (tid < 160) {
        int b = tid / 5, o = tid % 5;
        const float* hp = hid_s + b * 192 + ((o < 2) ? 0 : (o < 4) ? 64 : 128);
        const float* wp;
        float a;
        if (o == 0)      { wp = p.W_p2;      a = __ldg(p.b_p2); }
        else if (o == 1) { wp = p.W_p2 + 64; a = __ldg(p.b_p2 + 1); }
        else if (o == 2) { wp = p.W_s2;      a = __ldg(p.b_s2); }
        else if (o == 3) { wp = p.W_s2 + 64; a = __ldg(p.b_s2 + 1); }
        else             { wp = p.W_c2;      a = __ldg(p.b_c2); }
        #pragma unroll
        for (int k4 = 0; k4 < 16; k4++) {
            float4 hv = *(const float4*)(hp + 4 * k4);
            float4 wv = __ldg((const float4*)wp + k4);
            a = fmaf(hv.x, wv.x, a);
            a = fmaf(hv.y, wv.y, a);
            a = fmaf(hv.z, wv.z, a);
            a = fmaf(hv.w, wv.w, a);
        }
        fin_s[b * 5 + o] = a;
    }
    __syncthreads();

    // ============ Phase B5: box decode + output ============
    if (tid < 32) {
        int b = tid;
        float4 bx = __ldg((const float4*)p.boxes + (box0 + b));
        float cx = (bx.x + bx.z) * 0.5f, cy = (bx.y + bx.w) * 0.5f;
        float wd = bx.z - bx.x, hg = bx.w - bx.y;
        float ncx = cx + fin_s[b * 5 + 0];
        float ncy = cy + fin_s[b * 5 + 1];
        float nw = wd * __expf(fin_s[b * 5 + 2]);
        float nh = hg * __expf(fin_s[b * 5 + 3]);
        float conf = sig_(fin_s[b * 5 + 4]);
        float* op = p.out + (box0 + b) * 5;
        op[0] = ncx - nw * 0.5f;
        op[1] = ncy - nh * 0.5f;
        op[2] = ncx + nw * 0.5f;
        op[3] = ncy + nh * 0.5f;
        op[4] = conf;
    }
}

extern "C" void kernel_launch(void* const* d_in, const int* in_sizes, int n_in,
                              void* d_out, int out_size) {
    (void)in_sizes; (void)n_in; (void)out_size;
    Params p;
    p.mv       = (const float*)d_in[0];
    p.boxes    = (const float*)d_in[1];
    p.W_stats  = (const float*)d_in[2];
    p.b_stats  = (const float*)d_in[3];
    p.g_stats  = (const float*)d_in[4];
    p.be_stats = (const float*)d_in[5];
    p.W_b1     = (const float*)d_in[6];
    p.b_b1     = (const float*)d_in[7];
    p.g_b1     = (const float*)d_in[8];
    p.be_b1    = (const float*)d_in[9];
    p.W_b2     = (const float*)d_in[10];
    p.b_b2     = (const float*)d_in[11];
    p.g_b2     = (const float*)d_in[12];
    p.be_b2    = (const float*)d_in[13];
    p.W_ih     = (const float*)d_in[14];
    p.W_hh     = (const float*)d_in[15];
    p.b_ih     = (const float*)d_in[16];
    p.b_hh     = (const float*)d_in[17];
    p.W_p1     = (const float*)d_in[18];
    p.b_p1     = (const float*)d_in[19];
    p.W_p2     = (const float*)d_in[20];
    p.b_p2     = (const float*)d_in[21];
    p.W_s1     = (const float*)d_in[22];
    p.b_s1     = (const float*)d_in[23];
    p.W_s2     = (const float*)d_in[24];
    p.b_s2     = (const float*)d_in[25];
    p.W_c1     = (const float*)d_in[26];
    p.b_c1     = (const float*)d_in[27];
    p.W_c2     = (const float*)d_in[28];
    p.b_c2     = (const float*)d_in[29];
    p.out      = (float*)d_out;

    cudaFuncSetAttribute(tracker_fused_kernel,
                         cudaFuncAttributeMaxDynamicSharedMemorySize, SMEM_BYTES);
    tracker_fused_kernel<<<128, NT, SMEM_BYTES>>>(p);
}